// round 1
// baseline (speedup 1.0000x reference)
#include <cuda_runtime.h>

// Problem constants (fixed shapes from reference: B=32, T=1024, D=1024, U=1024)
#define BB 32
#define TT 1024
#define DD 1024
#define NCHUNK 16
#define TC (TT / NCHUNK)   // 64 timesteps per chunk
#define D4 (DD / 4)        // 256 float4 per row

// Scratch for partial sums: [B, NCHUNK, D] floats = 32*16*1024*4 = 2 MB
__device__ float4 g_partial[BB * NCHUNK * D4];

// Stage 1: block (b, chunk). Each of 256 threads owns one float4 column slice,
// sums TC=64 timesteps. Fully coalesced (warp reads contiguous 512B per row),
// 64 independent loads per thread unrolled for MLP.
__global__ __launch_bounds__(D4) void partial_sum_kernel(const float4* __restrict__ vals) {
    const int b = blockIdx.x;   // 0..31
    const int c = blockIdx.y;   // 0..15
    const int d4 = threadIdx.x; // 0..255

    const float4* __restrict__ p =
        vals + ((size_t)b * TT + (size_t)c * TC) * D4 + d4;

    float x = 0.f, y = 0.f, z = 0.f, w = 0.f;
#pragma unroll 16
    for (int t = 0; t < TC; ++t) {
        float4 v = p[(size_t)t * D4];
        x += v.x; y += v.y; z += v.z; w += v.w;
    }
    float4 acc = make_float4(x, y, z, w);
    g_partial[(b * NCHUNK + c) * D4 + d4] = acc;
}

// Stage 2: finalize all three outputs.
//   out[0 .. B*D)             = context[b,d]   = sum of 16 partials
//   out[B*D .. B*D+B*T)       = attention = 1.0 (softmax over singleton axis)
//   out[B*D+B*T .. +B*T)      = coverage[b,t] = (float)t (cumsum of ones)
__global__ void finalize_kernel(float* __restrict__ out) {
    const int idx = blockIdx.x * blockDim.x + threadIdx.x;
    const int CTX = BB * DD;          // 32768
    const int AW_END = CTX + BB * TT; // 65536
    const int TOTAL = AW_END + BB * TT; // 98304

    if (idx < CTX) {
        const int b = idx / DD;
        const int d = idx % DD;
        const float* part = reinterpret_cast<const float*>(g_partial);
        float s = 0.f;
#pragma unroll
        for (int c = 0; c < NCHUNK; ++c) {
            s += part[(b * NCHUNK + c) * DD + d];
        }
        out[idx] = s;
    } else if (idx < AW_END) {
        out[idx] = 1.0f;
    } else if (idx < TOTAL) {
        const int j = idx - AW_END;
        const int t = j % TT;
        out[idx] = (float)t;
    }
}

extern "C" void kernel_launch(void* const* d_in, const int* in_sizes, int n_in,
                              void* d_out, int out_size) {
    // Input order: query, values, W1, b1, W2, b2, W3, b3, V, bV
    const float4* values = (const float4*)d_in[1];
    float* out = (float*)d_out;

    dim3 grid1(BB, NCHUNK);
    partial_sum_kernel<<<grid1, D4>>>(values);

    const int TOTAL = BB * DD + 2 * BB * TT; // 98304
    finalize_kernel<<<(TOTAL + 255) / 256, 256>>>(out);
}